// round 6
// baseline (speedup 1.0000x reference)
#include <cuda_runtime.h>
#include <cuda_fp16.h>
#include <math.h>

#define N_NODES 20000
#define N_EDGES 5000
#define D       128
#define ATT     32
#define ECAP    384
#define NCAP    128
#define LN_EPS  1e-5f
#define DEG_EPS 1e-12f
#define FULL    0xffffffffu

// ---------------- device scratch ----------------
__device__ int   g_edge_cnt[N_EDGES];
__device__ int   g_node_cnt[N_NODES];
__device__ int   g_edge_nodes[N_EDGES * ECAP];
__device__ int   g_node_edges[N_NODES * NCAP];
__device__ uint2  g_x[N_NODES * 32];        // fp16 features (256B rows)
__device__ uint2  g_edge_h[N_EDGES * 32];   // fp16 edge means
__device__ float4 g_edge_out[N_EDGES * 32]; // fp32 final edge_out
__device__ float g_logits[N_EDGES];

// ---------------- fp16 helpers ----------------
__device__ __forceinline__ uint2 f4_to_h4(float4 v) {
    __half2 a = __floats2half2_rn(v.x, v.y);
    __half2 b = __floats2half2_rn(v.z, v.w);
    uint2 r; r.x = *(unsigned*)&a; r.y = *(unsigned*)&b; return r;
}
__device__ __forceinline__ __half2 u2h(unsigned u) { return *(__half2*)&u; }

// ---------------- zero counters (must precede build's atomics) ----------------
__global__ void zero_kernel() {
    int i = blockIdx.x * blockDim.x + threadIdx.x;
    if (i < N_EDGES) g_edge_cnt[i] = 0;
    if (i < N_NODES) g_node_cnt[i] = 0;
}

// ---------------- build adjacency + convert x0 -> fp16 (one DRAM pass) ----------------
__global__ void build_kernel(const float* __restrict__ H, const float4* __restrict__ x0) {
    long long idx = (long long)blockIdx.x * blockDim.x + threadIdx.x;
    long long stride = (long long)gridDim.x * blockDim.x;
    // x0 -> fp16 (independent of adjacency atomics)
    for (long long k = idx; k < (long long)N_NODES * 32; k += stride)
        g_x[k] = f4_to_h4(__ldg(&x0[k]));
    // dense H scan
    const long long total4 = (long long)N_NODES * N_EDGES / 4;
    const float4* H4 = (const float4*)H;
    for (long long qq = idx; qq < total4; qq += stride) {
        float4 v = __ldg(&H4[qq]);
        long long l = qq * 4;
        int n = (int)(l / N_EDGES);
        int e = (int)(l % N_EDGES);
        float vals[4] = {v.x, v.y, v.z, v.w};
        #pragma unroll
        for (int c = 0; c < 4; c++) {
            if (vals[c] != 0.0f) {
                int ee = e + c;
                int pe = atomicAdd(&g_edge_cnt[ee], 1);
                if (pe < ECAP) g_edge_nodes[ee * ECAP + pe] = n;
                int pn = atomicAdd(&g_node_cnt[n], 1);
                if (pn < NCAP) g_node_edges[n * NCAP + pn] = ee;
            }
        }
    }
}

// ---------------- V -> E mean (fp16, 4 warps/edge, unroll 8) ----------------
__global__ void __launch_bounds__(128) v2e_h_kernel() {
    int e = blockIdx.x;
    int w = threadIdx.x >> 5;
    int lane = threadIdx.x & 31;
    __shared__ float4 part[4][32];

    int deg = min(g_edge_cnt[e], ECAP);
    const int* lst = &g_edge_nodes[e * ECAP];
    int q = (deg + 3) >> 2;
    int start = w * q;
    int end = min(start + q, deg);

    __half2 z = __floats2half2_rn(0.f, 0.f);
    __half2 ax[8] = {z, z, z, z, z, z, z, z};
    __half2 ay[8] = {z, z, z, z, z, z, z, z};

    for (int base = start; base < end; base += 32) {
        int m = min(32, end - base);
        int idx = lst[base + min(lane, m - 1)];
        int k = 0;
        for (; k + 8 <= m; k += 8) {
            int nn[8];
            #pragma unroll
            for (int u = 0; u < 8; u++) nn[u] = __shfl_sync(FULL, idx, k + u);
            uint2 vv[8];
            #pragma unroll
            for (int u = 0; u < 8; u++) vv[u] = g_x[nn[u] * 32 + lane];
            #pragma unroll
            for (int u = 0; u < 8; u++) {
                ax[u] = __hadd2(ax[u], u2h(vv[u].x));
                ay[u] = __hadd2(ay[u], u2h(vv[u].y));
            }
        }
        for (; k < m; k++) {
            int n0 = __shfl_sync(FULL, idx, k);
            uint2 v0 = g_x[n0 * 32 + lane];
            ax[0] = __hadd2(ax[0], u2h(v0.x));
            ay[0] = __hadd2(ay[0], u2h(v0.y));
        }
    }
    float px = 0.f, py = 0.f, pz = 0.f, pw = 0.f;
    #pragma unroll
    for (int u = 0; u < 8; u++) {
        float2 fx = __half22float2(ax[u]);
        float2 fy = __half22float2(ay[u]);
        px += fx.x; py += fx.y; pz += fy.x; pw += fy.y;
    }
    part[w][lane] = make_float4(px, py, pz, pw);
    __syncthreads();
    if (w == 0) {
        float4 p0 = part[0][lane], p1 = part[1][lane], p2 = part[2][lane], p3 = part[3][lane];
        float s = 1.0f / fmaxf((float)deg, DEG_EPS);
        float4 r;
        r.x = ((p0.x + p1.x) + (p2.x + p3.x)) * s;
        r.y = ((p0.y + p1.y) + (p2.y + p3.y)) * s;
        r.z = ((p0.z + p1.z) + (p2.z + p3.z)) * s;
        r.w = ((p0.w + p1.w) + (p2.w + p3.w)) * s;
        g_edge_h[e * 32 + lane] = f4_to_h4(r);
    }
}

// ---------------- E -> V mean + residual + LayerNorm (warp/node, unroll 8) ----------------
__global__ void __launch_bounds__(256) e2v_ln_kernel(const float4* __restrict__ x0,
                                                     const float4* __restrict__ gamma,
                                                     const float4* __restrict__ beta) {
    int n = (blockIdx.x * blockDim.x + threadIdx.x) >> 5;
    int lane = threadIdx.x & 31;
    int deg = min(g_node_cnt[n], NCAP);
    const int* lst = &g_node_edges[n * NCAP];

    __half2 z = __floats2half2_rn(0.f, 0.f);
    __half2 ax[8] = {z, z, z, z, z, z, z, z};
    __half2 ay[8] = {z, z, z, z, z, z, z, z};

    for (int base = 0; base < deg; base += 32) {
        int m = min(32, deg - base);
        int idx = lst[base + min(lane, m - 1)];
        int k = 0;
        for (; k + 8 <= m; k += 8) {
            int ee[8];
            #pragma unroll
            for (int u = 0; u < 8; u++) ee[u] = __shfl_sync(FULL, idx, k + u);
            uint2 vv[8];
            #pragma unroll
            for (int u = 0; u < 8; u++) vv[u] = g_edge_h[ee[u] * 32 + lane];
            #pragma unroll
            for (int u = 0; u < 8; u++) {
                ax[u] = __hadd2(ax[u], u2h(vv[u].x));
                ay[u] = __hadd2(ay[u], u2h(vv[u].y));
            }
        }
        for (; k < m; k++) {
            int e0 = __shfl_sync(FULL, idx, k);
            uint2 v0 = g_edge_h[e0 * 32 + lane];
            ax[0] = __hadd2(ax[0], u2h(v0.x));
            ay[0] = __hadd2(ay[0], u2h(v0.y));
        }
    }
    float px = 0.f, py = 0.f, pz = 0.f, pw = 0.f;
    #pragma unroll
    for (int u = 0; u < 8; u++) {
        float2 fx = __half22float2(ax[u]);
        float2 fy = __half22float2(ay[u]);
        px += fx.x; py += fx.y; pz += fy.x; pw += fy.y;
    }
    float s = 1.0f / fmaxf((float)deg, DEG_EPS);
    float4 r = __ldg(&x0[n * 32 + lane]);
    float4 y;
    y.x = px * s + r.x;
    y.y = py * s + r.y;
    y.z = pz * s + r.z;
    y.w = pw * s + r.w;

    float sm = (y.x + y.y) + (y.z + y.w);
    #pragma unroll
    for (int o = 16; o > 0; o >>= 1) sm += __shfl_xor_sync(FULL, sm, o);
    float mu = sm * (1.0f / D);
    float4 dy;
    dy.x = y.x - mu; dy.y = y.y - mu; dy.z = y.z - mu; dy.w = y.w - mu;
    float s2 = (dy.x * dy.x + dy.y * dy.y) + (dy.z * dy.z + dy.w * dy.w);
    #pragma unroll
    for (int o = 16; o > 0; o >>= 1) s2 += __shfl_xor_sync(FULL, s2, o);
    float rstd = rsqrtf(s2 * (1.0f / D) + LN_EPS);
    float4 g = __ldg(&gamma[lane]);
    float4 bb = __ldg(&beta[lane]);
    float4 o4;
    o4.x = dy.x * rstd * g.x + bb.x;
    o4.y = dy.y * rstd * g.y + bb.y;
    o4.z = dy.z * rstd * g.z + bb.z;
    o4.w = dy.w * rstd * g.w + bb.w;
    g_x[n * 32 + lane] = f4_to_h4(o4);
}

// ---------------- final V -> E (fp32 accumulate) + fused attention logits ----------------
__global__ void __launch_bounds__(128) v2e_final_logits_kernel(const float* __restrict__ W,
                                                               const float* __restrict__ b,
                                                               const float* __restrict__ q) {
    int e = blockIdx.x;
    int w = threadIdx.x >> 5;
    int lane = threadIdx.x & 31;
    __shared__ float4 part[4][32];

    int deg = min(g_edge_cnt[e], ECAP);
    const int* lst = &g_edge_nodes[e * ECAP];
    int qq = (deg + 3) >> 2;
    int start = w * qq;
    int end = min(start + qq, deg);

    float4 fs = make_float4(0.f, 0.f, 0.f, 0.f);
    for (int base = start; base < end; base += 32) {
        int m = min(32, end - base);
        int idx = lst[base + min(lane, m - 1)];
        int k = 0;
        for (; k + 4 <= m; k += 4) {
            int n0 = __shfl_sync(FULL, idx, k);
            int n1 = __shfl_sync(FULL, idx, k + 1);
            int n2 = __shfl_sync(FULL, idx, k + 2);
            int n3 = __shfl_sync(FULL, idx, k + 3);
            uint2 v0 = g_x[n0 * 32 + lane];
            uint2 v1 = g_x[n1 * 32 + lane];
            uint2 v2 = g_x[n2 * 32 + lane];
            uint2 v3 = g_x[n3 * 32 + lane];
            float2 f0x = __half22float2(u2h(v0.x)), f0y = __half22float2(u2h(v0.y));
            float2 f1x = __half22float2(u2h(v1.x)), f1y = __half22float2(u2h(v1.y));
            float2 f2x = __half22float2(u2h(v2.x)), f2y = __half22float2(u2h(v2.y));
            float2 f3x = __half22float2(u2h(v3.x)), f3y = __half22float2(u2h(v3.y));
            fs.x += (f0x.x + f1x.x) + (f2x.x + f3x.x);
            fs.y += (f0x.y + f1x.y) + (f2x.y + f3x.y);
            fs.z += (f0y.x + f1y.x) + (f2y.x + f3y.x);
            fs.w += (f0y.y + f1y.y) + (f2y.y + f3y.y);
        }
        for (; k < m; k++) {
            int n0 = __shfl_sync(FULL, idx, k);
            uint2 v0 = g_x[n0 * 32 + lane];
            float2 fx = __half22float2(u2h(v0.x)), fy = __half22float2(u2h(v0.y));
            fs.x += fx.x; fs.y += fx.y; fs.z += fy.x; fs.w += fy.y;
        }
    }
    part[w][lane] = fs;
    __syncthreads();
    if (w == 0) {
        float4 p0 = part[0][lane], p1 = part[1][lane], p2 = part[2][lane], p3 = part[3][lane];
        float s = 1.0f / fmaxf((float)deg, DEG_EPS);
        float4 r;
        r.x = ((p0.x + p1.x) + (p2.x + p3.x)) * s;
        r.y = ((p0.y + p1.y) + (p2.y + p3.y)) * s;
        r.z = ((p0.z + p1.z) + (p2.z + p3.z)) * s;
        r.w = ((p0.w + p1.w) + (p2.w + p3.w)) * s;
        g_edge_out[e * 32 + lane] = r;

        // fused logits: warp 0 holds the full 128-dim row (4 dims/lane)
        float acc = 0.0f;
        #pragma unroll 8
        for (int k = 0; k < 32; k++) {
            float fx = __shfl_sync(FULL, r.x, k);
            float fy = __shfl_sync(FULL, r.y, k);
            float fz = __shfl_sync(FULL, r.z, k);
            float fw = __shfl_sync(FULL, r.w, k);
            acc += fx * __ldg(&W[(4 * k + 0) * ATT + lane]);
            acc += fy * __ldg(&W[(4 * k + 1) * ATT + lane]);
            acc += fz * __ldg(&W[(4 * k + 2) * ATT + lane]);
            acc += fw * __ldg(&W[(4 * k + 3) * ATT + lane]);
        }
        float t = tanhf(acc + __ldg(&b[lane])) * __ldg(&q[lane]);
        #pragma unroll
        for (int o = 16; o > 0; o >>= 1) t += __shfl_xor_sync(FULL, t, o);
        if (lane == 0) g_logits[e] = t;
    }
}

// ---------------- softmax + pool fused: 4 blocks x 1024 (32 dims per block) ----------------
__global__ void __launch_bounds__(1024) softmax_pool_kernel(float* __restrict__ out) {
    __shared__ float sc[N_EDGES];   // unnormalized scores
    __shared__ float red[32];
    int t = threadIdx.x;
    int wid = t >> 5;
    int lane = t & 31;

    // block-wide max
    float m = -1e30f;
    for (int e = t; e < N_EDGES; e += 1024) m = fmaxf(m, g_logits[e]);
    #pragma unroll
    for (int o = 16; o > 0; o >>= 1) m = fmaxf(m, __shfl_xor_sync(FULL, m, o));
    if (lane == 0) red[wid] = m;
    __syncthreads();
    if (t < 32) {
        float v = red[t];
        #pragma unroll
        for (int o = 16; o > 0; o >>= 1) v = fmaxf(v, __shfl_xor_sync(FULL, v, o));
        if (t == 0) red[0] = v;
    }
    __syncthreads();
    float mx = red[0];
    __syncthreads();
    // exp + sum
    float s = 0.0f;
    for (int e = t; e < N_EDGES; e += 1024) {
        float v = expf(g_logits[e] - mx);
        sc[e] = v;
        s += v;
    }
    #pragma unroll
    for (int o = 16; o > 0; o >>= 1) s += __shfl_xor_sync(FULL, s, o);
    if (lane == 0) red[wid] = s;
    __syncthreads();
    if (t < 32) {
        float v = red[t];
        #pragma unroll
        for (int o = 16; o > 0; o >>= 1) v += __shfl_xor_sync(FULL, v, o);
        if (t == 0) red[0] = v;
    }
    __syncthreads();
    float inv = 1.0f / red[0];

    // pool: warp per dim
    int d = blockIdx.x * 32 + wid;
    const float* eo = (const float*)g_edge_out;
    float acc = 0.0f;
    #pragma unroll 4
    for (int e = lane; e < N_EDGES; e += 32)
        acc += sc[e] * eo[e * D + d];
    #pragma unroll
    for (int o = 16; o > 0; o >>= 1) acc += __shfl_xor_sync(FULL, acc, o);
    if (lane == 0) out[d] = acc * inv;
}

// ---------------- launch ----------------
extern "C" void kernel_launch(void* const* d_in, const int* in_sizes, int n_in,
                              void* d_out, int out_size) {
    const float* x0    = (const float*)d_in[0];
    const float* H     = (const float*)d_in[1];
    const float* gamma = (const float*)d_in[2];
    const float* beta  = (const float*)d_in[3];
    const float* W     = (const float*)d_in[4];
    const float* b     = (const float*)d_in[5];
    const float* q     = (const float*)d_in[6];
    float* out = (float*)d_out;

    zero_kernel<<<(N_NODES + 255) / 256, 256>>>();
    build_kernel<<<4096, 256>>>(H, (const float4*)x0);

    for (int l = 0; l < 4; l++) {
        v2e_h_kernel<<<N_EDGES, 128>>>();
        e2v_ln_kernel<<<N_NODES / 8, 256>>>((const float4*)x0,
                                            (const float4*)gamma,
                                            (const float4*)beta);
    }
    v2e_final_logits_kernel<<<N_EDGES, 128>>>(W, b, q);
    softmax_pool_kernel<<<4, 1024>>>(out);
}

// round 7
// speedup vs baseline: 1.0348x; 1.0348x over previous
#include <cuda_runtime.h>
#include <cuda_fp16.h>
#include <math.h>

#define N_NODES 20000
#define N_EDGES 5000
#define D       128
#define ATT     32
#define ECAP    384
#define NCAP    128
#define LN_EPS  1e-5f
#define DEG_EPS 1e-12f
#define FULL    0xffffffffu
#define E4      (N_EDGES / 4)    // 1250 float4 per H row

// ---------------- device scratch ----------------
__device__ int   g_edge_cnt[N_EDGES];
__device__ int   g_node_cnt[N_NODES];
__device__ int   g_edge_nodes[N_EDGES * ECAP];
__device__ int   g_node_edges[N_NODES * NCAP];
__device__ uint2  g_x[N_NODES * 32];        // fp16 features (256B rows)
__device__ uint2  g_edge_h[N_EDGES * 32];   // fp16 edge means
__device__ float4 g_edge_out[N_EDGES * 32]; // fp32 final edge_out
__device__ float g_logits[N_EDGES];

// ---------------- fp16 helpers ----------------
__device__ __forceinline__ uint2 f4_to_h4(float4 v) {
    __half2 a = __floats2half2_rn(v.x, v.y);
    __half2 b = __floats2half2_rn(v.z, v.w);
    uint2 r; r.x = *(unsigned*)&a; r.y = *(unsigned*)&b; return r;
}
__device__ __forceinline__ float4 h4_to_f4(uint2 v) {
    float2 a = __half22float2(*(__half2*)&v.x);
    float2 b = __half22float2(*(__half2*)&v.y);
    return make_float4(a.x, a.y, b.x, b.y);
}
__device__ __forceinline__ __half2 u2h(unsigned u) { return *(__half2*)&u; }

// ---------------- zero counters (must precede build's atomics) ----------------
__global__ void zero_kernel() {
    int i = blockIdx.x * blockDim.x + threadIdx.x;
    if (i < N_EDGES) g_edge_cnt[i] = 0;
    if (i < N_NODES) g_node_cnt[i] = 0;
}

// ---------------- build adjacency + convert x0 -> fp16 (one DRAM pass) ----------------
__global__ void build_kernel(const float* __restrict__ H, const float4* __restrict__ x0) {
    int idx = blockIdx.x * blockDim.x + threadIdx.x;
    int stride = gridDim.x * blockDim.x;
    // x0 -> fp16 (independent of adjacency atomics)
    for (int k = idx; k < N_NODES * 32; k += stride)
        g_x[k] = f4_to_h4(__ldg(&x0[k]));
    // dense H scan, 32-bit indexing (25M float4 < 2^31)
    const int total4 = N_NODES * E4;
    const float4* H4 = (const float4*)H;
    for (int qq = idx; qq < total4; qq += stride) {
        float4 v = __ldg(&H4[qq]);
        int n = qq / E4;
        int e = (qq - n * E4) * 4;
        float vals[4] = {v.x, v.y, v.z, v.w};
        #pragma unroll
        for (int c = 0; c < 4; c++) {
            if (vals[c] != 0.0f) {
                int ee = e + c;
                int pe = atomicAdd(&g_edge_cnt[ee], 1);
                if (pe < ECAP) g_edge_nodes[ee * ECAP + pe] = n;
                int pn = atomicAdd(&g_node_cnt[n], 1);
                if (pn < NCAP) g_node_edges[n * NCAP + pn] = ee;
            }
        }
    }
}

// ---------------- V -> E mean (fp16, 4 warps/edge, unroll 4 — R3 form) ----------------
__global__ void __launch_bounds__(128) v2e_h_kernel() {
    int e = blockIdx.x;
    int w = threadIdx.x >> 5;
    int lane = threadIdx.x & 31;
    __shared__ float4 part[4][32];

    int deg = min(g_edge_cnt[e], ECAP);
    const int* lst = &g_edge_nodes[e * ECAP];
    int q = (deg + 3) >> 2;
    int start = w * q;
    int end = min(start + q, deg);

    __half2 z = __floats2half2_rn(0.f, 0.f);
    __half2 a0x = z, a0y = z, a1x = z, a1y = z, a2x = z, a2y = z, a3x = z, a3y = z;

    for (int base = start; base < end; base += 32) {
        int m = min(32, end - base);
        int idx = lst[base + min(lane, m - 1)];
        int k = 0;
        for (; k + 4 <= m; k += 4) {
            int n0 = __shfl_sync(FULL, idx, k);
            int n1 = __shfl_sync(FULL, idx, k + 1);
            int n2 = __shfl_sync(FULL, idx, k + 2);
            int n3 = __shfl_sync(FULL, idx, k + 3);
            uint2 v0 = g_x[n0 * 32 + lane];
            uint2 v1 = g_x[n1 * 32 + lane];
            uint2 v2 = g_x[n2 * 32 + lane];
            uint2 v3 = g_x[n3 * 32 + lane];
            a0x = __hadd2(a0x, u2h(v0.x)); a0y = __hadd2(a0y, u2h(v0.y));
            a1x = __hadd2(a1x, u2h(v1.x)); a1y = __hadd2(a1y, u2h(v1.y));
            a2x = __hadd2(a2x, u2h(v2.x)); a2y = __hadd2(a2y, u2h(v2.y));
            a3x = __hadd2(a3x, u2h(v3.x)); a3y = __hadd2(a3y, u2h(v3.y));
        }
        for (; k < m; k++) {
            int n0 = __shfl_sync(FULL, idx, k);
            uint2 v0 = g_x[n0 * 32 + lane];
            a0x = __hadd2(a0x, u2h(v0.x)); a0y = __hadd2(a0y, u2h(v0.y));
        }
    }
    float2 sx0 = __half22float2(a0x), sx1 = __half22float2(a1x);
    float2 sx2 = __half22float2(a2x), sx3 = __half22float2(a3x);
    float2 sy0 = __half22float2(a0y), sy1 = __half22float2(a1y);
    float2 sy2 = __half22float2(a2y), sy3 = __half22float2(a3y);
    float4 p;
    p.x = (sx0.x + sx1.x) + (sx2.x + sx3.x);
    p.y = (sx0.y + sx1.y) + (sx2.y + sx3.y);
    p.z = (sy0.x + sy1.x) + (sy2.x + sy3.x);
    p.w = (sy0.y + sy1.y) + (sy2.y + sy3.y);
    part[w][lane] = p;
    __syncthreads();
    if (w == 0) {
        float4 p0 = part[0][lane], p1 = part[1][lane], p2 = part[2][lane], p3 = part[3][lane];
        float s = 1.0f / fmaxf((float)deg, DEG_EPS);
        float4 r;
        r.x = ((p0.x + p1.x) + (p2.x + p3.x)) * s;
        r.y = ((p0.y + p1.y) + (p2.y + p3.y)) * s;
        r.z = ((p0.z + p1.z) + (p2.z + p3.z)) * s;
        r.w = ((p0.w + p1.w) + (p2.w + p3.w)) * s;
        g_edge_h[e * 32 + lane] = f4_to_h4(r);
    }
}

// ---------------- E -> V mean + residual + LayerNorm (warp/node, unroll 4 — R3 form) ----------------
__global__ void __launch_bounds__(256) e2v_ln_kernel(const float4* __restrict__ x0,
                                                     const float4* __restrict__ gamma,
                                                     const float4* __restrict__ beta) {
    int n = (blockIdx.x * blockDim.x + threadIdx.x) >> 5;
    int lane = threadIdx.x & 31;
    int deg = min(g_node_cnt[n], NCAP);
    const int* lst = &g_node_edges[n * NCAP];

    __half2 z = __floats2half2_rn(0.f, 0.f);
    __half2 a0x = z, a0y = z, a1x = z, a1y = z, a2x = z, a2y = z, a3x = z, a3y = z;

    for (int base = 0; base < deg; base += 32) {
        int m = min(32, deg - base);
        int idx = lst[base + min(lane, m - 1)];
        int k = 0;
        for (; k + 4 <= m; k += 4) {
            int e0 = __shfl_sync(FULL, idx, k);
            int e1 = __shfl_sync(FULL, idx, k + 1);
            int e2 = __shfl_sync(FULL, idx, k + 2);
            int e3 = __shfl_sync(FULL, idx, k + 3);
            uint2 v0 = g_edge_h[e0 * 32 + lane];
            uint2 v1 = g_edge_h[e1 * 32 + lane];
            uint2 v2 = g_edge_h[e2 * 32 + lane];
            uint2 v3 = g_edge_h[e3 * 32 + lane];
            a0x = __hadd2(a0x, u2h(v0.x)); a0y = __hadd2(a0y, u2h(v0.y));
            a1x = __hadd2(a1x, u2h(v1.x)); a1y = __hadd2(a1y, u2h(v1.y));
            a2x = __hadd2(a2x, u2h(v2.x)); a2y = __hadd2(a2y, u2h(v2.y));
            a3x = __hadd2(a3x, u2h(v3.x)); a3y = __hadd2(a3y, u2h(v3.y));
        }
        for (; k < m; k++) {
            int e0 = __shfl_sync(FULL, idx, k);
            uint2 v0 = g_edge_h[e0 * 32 + lane];
            a0x = __hadd2(a0x, u2h(v0.x)); a0y = __hadd2(a0y, u2h(v0.y));
        }
    }
    float2 sx0 = __half22float2(a0x), sx1 = __half22float2(a1x);
    float2 sx2 = __half22float2(a2x), sx3 = __half22float2(a3x);
    float2 sy0 = __half22float2(a0y), sy1 = __half22float2(a1y);
    float2 sy2 = __half22float2(a2y), sy3 = __half22float2(a3y);
    float s = 1.0f / fmaxf((float)deg, DEG_EPS);
    float4 r = __ldg(&x0[n * 32 + lane]);
    float4 y;
    y.x = ((sx0.x + sx1.x) + (sx2.x + sx3.x)) * s + r.x;
    y.y = ((sx0.y + sx1.y) + (sx2.y + sx3.y)) * s + r.y;
    y.z = ((sy0.x + sy1.x) + (sy2.x + sy3.x)) * s + r.z;
    y.w = ((sy0.y + sy1.y) + (sy2.y + sy3.y)) * s + r.w;

    float sm = (y.x + y.y) + (y.z + y.w);
    #pragma unroll
    for (int o = 16; o > 0; o >>= 1) sm += __shfl_xor_sync(FULL, sm, o);
    float mu = sm * (1.0f / D);
    float4 dy;
    dy.x = y.x - mu; dy.y = y.y - mu; dy.z = y.z - mu; dy.w = y.w - mu;
    float s2 = (dy.x * dy.x + dy.y * dy.y) + (dy.z * dy.z + dy.w * dy.w);
    #pragma unroll
    for (int o = 16; o > 0; o >>= 1) s2 += __shfl_xor_sync(FULL, s2, o);
    float rstd = rsqrtf(s2 * (1.0f / D) + LN_EPS);
    float4 g = __ldg(&gamma[lane]);
    float4 bb = __ldg(&beta[lane]);
    float4 o4;
    o4.x = dy.x * rstd * g.x + bb.x;
    o4.y = dy.y * rstd * g.y + bb.y;
    o4.z = dy.z * rstd * g.z + bb.z;
    o4.w = dy.w * rstd * g.w + bb.w;
    g_x[n * 32 + lane] = f4_to_h4(o4);
}

// ---------------- final V -> E (fp32 accumulate) + fused attention logits ----------------
__global__ void __launch_bounds__(128) v2e_final_logits_kernel(const float* __restrict__ W,
                                                               const float* __restrict__ b,
                                                               const float* __restrict__ q) {
    int e = blockIdx.x;
    int w = threadIdx.x >> 5;
    int lane = threadIdx.x & 31;
    __shared__ float4 part[4][32];

    int deg = min(g_edge_cnt[e], ECAP);
    const int* lst = &g_edge_nodes[e * ECAP];
    int qq = (deg + 3) >> 2;
    int start = w * qq;
    int end = min(start + qq, deg);

    float4 fs = make_float4(0.f, 0.f, 0.f, 0.f);
    for (int base = start; base < end; base += 32) {
        int m = min(32, end - base);
        int idx = lst[base + min(lane, m - 1)];
        int k = 0;
        for (; k + 4 <= m; k += 4) {
            int n0 = __shfl_sync(FULL, idx, k);
            int n1 = __shfl_sync(FULL, idx, k + 1);
            int n2 = __shfl_sync(FULL, idx, k + 2);
            int n3 = __shfl_sync(FULL, idx, k + 3);
            float4 f0 = h4_to_f4(g_x[n0 * 32 + lane]);
            float4 f1 = h4_to_f4(g_x[n1 * 32 + lane]);
            float4 f2 = h4_to_f4(g_x[n2 * 32 + lane]);
            float4 f3 = h4_to_f4(g_x[n3 * 32 + lane]);
            fs.x += (f0.x + f1.x) + (f2.x + f3.x);
            fs.y += (f0.y + f1.y) + (f2.y + f3.y);
            fs.z += (f0.z + f1.z) + (f2.z + f3.z);
            fs.w += (f0.w + f1.w) + (f2.w + f3.w);
        }
        for (; k < m; k++) {
            int n0 = __shfl_sync(FULL, idx, k);
            float4 f0 = h4_to_f4(g_x[n0 * 32 + lane]);
            fs.x += f0.x; fs.y += f0.y; fs.z += f0.z; fs.w += f0.w;
        }
    }
    part[w][lane] = fs;
    __syncthreads();
    if (w == 0) {
        float4 p0 = part[0][lane], p1 = part[1][lane], p2 = part[2][lane], p3 = part[3][lane];
        float s = 1.0f / fmaxf((float)deg, DEG_EPS);
        float4 r;
        r.x = ((p0.x + p1.x) + (p2.x + p3.x)) * s;
        r.y = ((p0.y + p1.y) + (p2.y + p3.y)) * s;
        r.z = ((p0.z + p1.z) + (p2.z + p3.z)) * s;
        r.w = ((p0.w + p1.w) + (p2.w + p3.w)) * s;
        g_edge_out[e * 32 + lane] = r;

        // fused logits: warp 0 holds the full 128-dim row (4 dims/lane)
        float acc = 0.0f;
        #pragma unroll 8
        for (int k = 0; k < 32; k++) {
            float fx = __shfl_sync(FULL, r.x, k);
            float fy = __shfl_sync(FULL, r.y, k);
            float fz = __shfl_sync(FULL, r.z, k);
            float fw = __shfl_sync(FULL, r.w, k);
            acc += fx * __ldg(&W[(4 * k + 0) * ATT + lane]);
            acc += fy * __ldg(&W[(4 * k + 1) * ATT + lane]);
            acc += fz * __ldg(&W[(4 * k + 2) * ATT + lane]);
            acc += fw * __ldg(&W[(4 * k + 3) * ATT + lane]);
        }
        float t = tanhf(acc + __ldg(&b[lane])) * __ldg(&q[lane]);
        #pragma unroll
        for (int o = 16; o > 0; o >>= 1) t += __shfl_xor_sync(FULL, t, o);
        if (lane == 0) g_logits[e] = t;
    }
}

// ---------------- softmax + pool fused: 4 blocks x 1024 (32 dims per block) ----------------
__global__ void __launch_bounds__(1024) softmax_pool_kernel(float* __restrict__ out) {
    __shared__ float sc[N_EDGES];   // unnormalized scores
    __shared__ float red[32];
    int t = threadIdx.x;
    int wid = t >> 5;
    int lane = t & 31;

    float m = -1e30f;
    for (int e = t; e < N_EDGES; e += 1024) m = fmaxf(m, g_logits[e]);
    #pragma unroll
    for (int o = 16; o > 0; o >>= 1) m = fmaxf(m, __shfl_xor_sync(FULL, m, o));
    if (lane == 0) red[wid] = m;
    __syncthreads();
    if (t < 32) {
        float v = red[t];
        #pragma unroll
        for (int o = 16; o > 0; o >>= 1) v = fmaxf(v, __shfl_xor_sync(FULL, v, o));
        if (t == 0) red[0] = v;
    }
    __syncthreads();
    float mx = red[0];
    __syncthreads();
    float s = 0.0f;
    for (int e = t; e < N_EDGES; e += 1024) {
        float v = expf(g_logits[e] - mx);
        sc[e] = v;
        s += v;
    }
    #pragma unroll
    for (int o = 16; o > 0; o >>= 1) s += __shfl_xor_sync(FULL, s, o);
    if (lane == 0) red[wid] = s;
    __syncthreads();
    if (t < 32) {
        float v = red[t];
        #pragma unroll
        for (int o = 16; o > 0; o >>= 1) v += __shfl_xor_sync(FULL, v, o);
        if (t == 0) red[0] = v;
    }
    __syncthreads();
    float inv = 1.0f / red[0];

    int d = blockIdx.x * 32 + wid;
    const float* eo = (const float*)g_edge_out;
    float acc = 0.0f;
    #pragma unroll 4
    for (int e = lane; e < N_EDGES; e += 32)
        acc += sc[e] * eo[e * D + d];
    #pragma unroll
    for (int o = 16; o > 0; o >>= 1) acc += __shfl_xor_sync(FULL, acc, o);
    if (lane == 0) out[d] = acc * inv;
}

// ---------------- launch ----------------
extern "C" void kernel_launch(void* const* d_in, const int* in_sizes, int n_in,
                              void* d_out, int out_size) {
    const float* x0    = (const float*)d_in[0];
    const float* H     = (const float*)d_in[1];
    const float* gamma = (const float*)d_in[2];
    const float* beta  = (const float*)d_in[3];
    const float* W     = (const float*)d_in[4];
    const float* b     = (const float*)d_in[5];
    const float* q     = (const float*)d_in[6];
    float* out = (float*)d_out;

    zero_kernel<<<(N_NODES + 255) / 256, 256>>>();
    build_kernel<<<4096, 256>>>(H, (const float4*)x0);

    for (int l = 0; l < 4; l++) {
        v2e_h_kernel<<<N_EDGES, 128>>>();
        e2v_ln_kernel<<<N_NODES / 8, 256>>>((const float4*)x0,
                                            (const float4*)gamma,
                                            (const float4*)beta);
    }
    v2e_final_logits_kernel<<<N_EDGES, 128>>>(W, b, q);
    softmax_pool_kernel<<<4, 1024>>>(out);
}